// round 3
// baseline (speedup 1.0000x reference)
#include <cuda_runtime.h>

#define NP 262144          // 2048*128 points
#define GD3 884736         // 96^3

// ---------------- scratch (static device globals; allocation-free) ----------------
__device__ float g_feats[NP * 32];
__device__ float g_dfp[NP * 96];            // [P][3][32] d feat / d p
__device__ float g_H1[(size_t)NP * 256];
__device__ float g_H2[(size_t)NP * 256];
__device__ float g_geo[NP * 15];
__device__ float g_W1T[256 * 256];          // W1T[j][i] = W1[i][j]
__device__ float g_W0T[256 * 35];           // W0T[j][i] = W0[i][j]

// ---------------- weight transpose ----------------
__global__ void k_transpose(const float* __restrict__ W0, const float* __restrict__ W1) {
    int total = 256 * 256 + 256 * 35;
    for (int g = blockIdx.x * blockDim.x + threadIdx.x; g < total; g += gridDim.x * blockDim.x) {
        if (g < 65536) {
            int j = g >> 8, i = g & 255;
            g_W1T[j * 256 + i] = W1[i * 256 + j];
        } else {
            int t = g - 65536;
            int j = t / 35, i = t - j * 35;
            g_W0T[t] = W0[i * 256 + j];
        }
    }
}

// ---------------- trilinear sampling: feats + d feat/d p ----------------
__global__ void k_sample(const float* __restrict__ pts,
                         const float* __restrict__ vol0,
                         const float* __restrict__ vol1) {
    extern __shared__ float sm[];
    float* sFeat = sm;            // 64*33 (padded)
    float* sDfp  = sm + 2112;     // 64*97 (padded)
    int tid = threadIdx.x;
    int p = blockIdx.x * 64 + tid;

    float px = pts[p * 3 + 0], py = pts[p * 3 + 1], pz = pts[p * 3 + 2];
    float x = px * 95.f, y = py * 95.f, z = pz * 95.f;
    int x0 = (int)floorf(x); x0 = min(max(x0, 0), 94);
    int y0 = (int)floorf(y); y0 = min(max(y0, 0), 94);
    int z0 = (int)floorf(z); z0 = min(max(z0, 0), 94);
    float xd = x - (float)x0, yd = y - (float)y0, zd = z - (float)z0;
    float wx0 = 1.f - xd, wx1 = xd;
    float wy0 = 1.f - yd, wy1 = yd;
    float wz0 = 1.f - zd, wz1 = zd;

    int base = (z0 * 96 + y0) * 96 + x0;
    const float* vols[2] = { vol0, vol1 };

    #pragma unroll
    for (int v = 0; v < 2; v++) {
        const float* vb = vols[v] + base;
        #pragma unroll 4
        for (int c = 0; c < 16; c++) {
            const float* q = vb + c * GD3;
            float v000 = __ldg(q);        float v001 = __ldg(q + 1);
            float v010 = __ldg(q + 96);   float v011 = __ldg(q + 97);
            float v100 = __ldg(q + 9216); float v101 = __ldg(q + 9217);
            float v110 = __ldg(q + 9312); float v111 = __ldg(q + 9313);
            float feat = wz0 * (wy0 * (v000 * wx0 + v001 * wx1) + wy1 * (v010 * wx0 + v011 * wx1))
                       + wz1 * (wy0 * (v100 * wx0 + v101 * wx1) + wy1 * (v110 * wx0 + v111 * wx1));
            float dfx = 95.f * (wz0 * (wy0 * (v001 - v000) + wy1 * (v011 - v010))
                              + wz1 * (wy0 * (v101 - v100) + wy1 * (v111 - v110)));
            float dfy = 95.f * (wz0 * (wx0 * (v010 - v000) + wx1 * (v011 - v001))
                              + wz1 * (wx0 * (v110 - v100) + wx1 * (v111 - v101)));
            float dfz = 95.f * (wy0 * (wx0 * (v100 - v000) + wx1 * (v101 - v001))
                              + wy1 * (wx0 * (v110 - v010) + wx1 * (v111 - v011)));
            // feature permutation: [f0 c0..7 | f1 c0..7 | f0 c8..15 | f1 c8..15]
            int fi = (c >> 3) * 16 + v * 8 + (c & 7);
            sFeat[tid * 33 + fi] = feat;
            sDfp[tid * 97 + fi]      = dfx;
            sDfp[tid * 97 + 32 + fi] = dfy;
            sDfp[tid * 97 + 64 + fi] = dfz;
        }
    }
    __syncthreads();
    int fb = blockIdx.x * 64 * 32;
    for (int t = tid; t < 2048; t += 64)
        g_feats[fb + t] = sFeat[(t >> 5) * 33 + (t & 31)];
    int db = blockIdx.x * 64 * 96;
    for (int t = tid; t < 6144; t += 64) {
        int pp = t / 96, q = t - pp * 96;
        g_dfp[db + t] = sDfp[pp * 97 + q];
    }
}

// ---------------- 64-point x 256-out tile GEMM (8x8 register microtile) ----------------
__device__ __forceinline__ void gemm64x256(
    const float* sA, int lda, const float* __restrict__ gW, int KD,
    const float* __restrict__ gBias, float* sOut, float* sW,
    bool do_relu, float* gOut, const float* gMask)
{
    int tid = threadIdx.x;
    int p0 = (tid >> 5) * 8;     // warp -> 8 points
    int j0 = (tid & 31) * 8;     // lane -> 8 output cols
    float acc[8][8];
    float b[8];
    #pragma unroll
    for (int j = 0; j < 8; j++) b[j] = gBias ? gBias[j0 + j] : 0.f;
    #pragma unroll
    for (int i = 0; i < 8; i++)
        #pragma unroll
        for (int j = 0; j < 8; j++) acc[i][j] = b[j];

    for (int k0 = 0; k0 < KD; k0 += 32) {
        int kc = KD - k0; if (kc > 32) kc = 32;
        __syncthreads();
        for (int t = tid; t < kc * 64; t += 256) {
            int r = t >> 6, c = t & 63;
            ((float4*)sW)[r * 64 + c] = ((const float4*)(gW + (size_t)(k0 + r) * 256))[c];
        }
        __syncthreads();
        if (kc == 32) {
            #pragma unroll
            for (int k = 0; k < 32; k++) {
                float a[8];
                #pragma unroll
                for (int i = 0; i < 8; i++) a[i] = sA[(p0 + i) * lda + k0 + k];
                float4 wA = *(const float4*)(sW + k * 256 + j0);
                float4 wB = *(const float4*)(sW + k * 256 + j0 + 4);
                float wv[8] = { wA.x, wA.y, wA.z, wA.w, wB.x, wB.y, wB.z, wB.w };
                #pragma unroll
                for (int i = 0; i < 8; i++)
                    #pragma unroll
                    for (int j = 0; j < 8; j++) acc[i][j] = fmaf(a[i], wv[j], acc[i][j]);
            }
        } else {
            for (int k = 0; k < kc; k++) {
                float a[8];
                #pragma unroll
                for (int i = 0; i < 8; i++) a[i] = sA[(p0 + i) * lda + k0 + k];
                float4 wA = *(const float4*)(sW + k * 256 + j0);
                float4 wB = *(const float4*)(sW + k * 256 + j0 + 4);
                float wv[8] = { wA.x, wA.y, wA.z, wA.w, wB.x, wB.y, wB.z, wB.w };
                #pragma unroll
                for (int i = 0; i < 8; i++)
                    #pragma unroll
                    for (int j = 0; j < 8; j++) acc[i][j] = fmaf(a[i], wv[j], acc[i][j]);
            }
        }
    }
    #pragma unroll
    for (int i = 0; i < 8; i++) {
        float vv[8];
        #pragma unroll
        for (int j = 0; j < 8; j++) {
            float v = acc[i][j];
            if (do_relu) v = fmaxf(v, 0.f);
            vv[j] = v;
        }
        if (gMask) {
            float4 m0 = *(const float4*)(gMask + (size_t)(p0 + i) * 256 + j0);
            float4 m1 = *(const float4*)(gMask + (size_t)(p0 + i) * 256 + j0 + 4);
            float mm[8] = { m0.x, m0.y, m0.z, m0.w, m1.x, m1.y, m1.z, m1.w };
            #pragma unroll
            for (int j = 0; j < 8; j++) vv[j] = (mm[j] > 0.f) ? vv[j] : 0.f;
        }
        float4 o0 = make_float4(vv[0], vv[1], vv[2], vv[3]);
        float4 o1 = make_float4(vv[4], vv[5], vv[6], vv[7]);
        *(float4*)(sOut + (p0 + i) * 256 + j0)     = o0;
        *(float4*)(sOut + (p0 + i) * 256 + j0 + 4) = o1;
        if (gOut) {
            *(float4*)(gOut + (size_t)(p0 + i) * 256 + j0)     = o0;
            *(float4*)(gOut + (size_t)(p0 + i) * 256 + j0 + 4) = o1;
        }
    }
    __syncthreads();
}

// ---------------- forward MLP ----------------
__global__ __launch_bounds__(256) void k_forward(
    const float* __restrict__ pts,
    const float* __restrict__ W0, const float* __restrict__ b0,
    const float* __restrict__ W1, const float* __restrict__ b1,
    const float* __restrict__ W2, const float* __restrict__ b2,
    float* __restrict__ out)
{
    extern __shared__ float sm[];
    float* sW  = sm;             // 8192
    float* sH1 = sm + 8192;      // 16384
    float* sH2 = sm + 24576;     // 16384
    float* sX  = sm + 40960;     // 64*36
    int tid = threadIdx.x;
    int pb = blockIdx.x * 64;

    for (int t = tid; t < 192; t += 256) { int p = t / 3, a = t - p * 3; sX[p * 36 + a] = pts[(pb + p) * 3 + a]; }
    for (int t = tid; t < 2048; t += 256) { int p = t >> 5, c = t & 31; sX[p * 36 + 3 + c] = g_feats[pb * 32 + t]; }
    __syncthreads();

    gemm64x256(sX, 36, W0, 35, b0, sH1, sW, true, g_H1 + (size_t)pb * 256, nullptr);
    gemm64x256(sH1, 256, W1, 256, b1, sH2, sW, true, g_H2 + (size_t)pb * 256, nullptr);

    // layer 3: 256 -> 16  (W2 staged in sW)
    for (int t = tid; t < 1024; t += 256) ((float4*)sW)[t] = ((const float4*)W2)[t];
    __syncthreads();
    int jc = tid & 15, pr = tid >> 4;
    float acc[4];
    float bb = b2[jc];
    #pragma unroll
    for (int i = 0; i < 4; i++) acc[i] = bb;
    for (int k = 0; k < 256; k++) {
        float wv = sW[k * 16 + jc];
        #pragma unroll
        for (int i = 0; i < 4; i++) acc[i] = fmaf(sH2[(pr * 4 + i) * 256 + k], wv, acc[i]);
    }
    #pragma unroll
    for (int i = 0; i < 4; i++) {
        int pt = pb + pr * 4 + i;
        if (jc == 0) out[(size_t)NP * 4 + pt] = acc[i];
        else         g_geo[pt * 15 + jc - 1] = acc[i];
    }
}

// ---------------- backward: gradients of sdf wrt points ----------------
__global__ __launch_bounds__(256) void k_backward(
    const float* __restrict__ W2, float* __restrict__ out)
{
    extern __shared__ float sm[];
    float* sW   = sm;            // 8960 (k-chunk / W0T)
    float* sG2  = sm + 8960;     // 16384
    float* sG1  = sm + 25344;    // 16384
    float* sGx  = sm + 41728;    // 2240
    float* sDfp = sm + 43968;    // 6144
    float* sB   = sm + 50112;    // 256
    int tid = threadIdx.x;
    int pb = blockIdx.x * 64;

    sB[tid] = W2[tid * 16];      // W2 column 0
    __syncthreads();

    const float4* h2 = (const float4*)(g_H2 + (size_t)pb * 256);
    for (int t = tid; t < 4096; t += 256) {
        float4 h = h2[t];
        int j = (t & 63) * 4;
        float4 g;
        g.x = h.x > 0.f ? sB[j]     : 0.f;
        g.y = h.y > 0.f ? sB[j + 1] : 0.f;
        g.z = h.z > 0.f ? sB[j + 2] : 0.f;
        g.w = h.w > 0.f ? sB[j + 3] : 0.f;
        ((float4*)sG2)[t] = g;
    }
    // G1 = (G2 @ W1^T) * (H1 > 0)
    gemm64x256(sG2, 256, g_W1T, 256, nullptr, sG1, sW, false, nullptr, g_H1 + (size_t)pb * 256);

    // Gx = G1 @ W0^T  (N = 35)
    for (int t = tid; t < 2240; t += 256) ((float4*)sW)[t] = ((const float4*)g_W0T)[t];
    for (int t = tid; t < 6144; t += 256) sDfp[t] = g_dfp[(size_t)pb * 96 + t];
    __syncthreads();
    for (int o = tid; o < 2240; o += 256) {
        int p = o / 35, i = o - p * 35;
        float a = 0.f;
        const float* gr = sG1 + p * 256;
        for (int k = 0; k < 256; k++) a = fmaf(gr[k], sW[k * 35 + i], a);
        sGx[o] = a;
    }
    __syncthreads();
    if (tid < 64) {
        int p = tid, pt = pb + p;
        float gx = sGx[p * 35], gy = sGx[p * 35 + 1], gz = sGx[p * 35 + 2];
        #pragma unroll
        for (int c = 0; c < 32; c++) {
            float q = sGx[p * 35 + 3 + c];
            gx = fmaf(q, sDfp[p * 96 + c],      gx);
            gy = fmaf(q, sDfp[p * 96 + 32 + c], gy);
            gz = fmaf(q, sDfp[p * 96 + 64 + c], gz);
        }
        out[(size_t)NP * 5 + pt * 3 + 0] = gx;
        out[(size_t)NP * 5 + pt * 3 + 1] = gy;
        out[(size_t)NP * 5 + pt * 3 + 2] = gz;
        float n = sqrtf(gx * gx + gy * gy + gz * gz);
        float inv = 1.f / fmaxf(n, 1e-12f);
        out[(size_t)NP * 8 + pt * 3 + 0] = gx * inv;
        out[(size_t)NP * 8 + pt * 3 + 1] = gy * inv;
        out[(size_t)NP * 8 + pt * 3 + 2] = gz * inv;
    }
}

// ---------------- RGB head + elementwise outputs ----------------
__global__ __launch_bounds__(256) void k_rgb(
    const float* __restrict__ pts, const float* __restrict__ dirs,
    const float* __restrict__ deltas,
    const float* __restrict__ Wr0, const float* __restrict__ br0,
    const float* __restrict__ Wr1, const float* __restrict__ br1,
    const float* __restrict__ beta, const float* __restrict__ variance,
    float* __restrict__ out)
{
    extern __shared__ float sm[];
    float* sW  = sm;             // 8192
    float* sHr = sm + 8192;      // 16384
    float* sX  = sm + 24576;     // 64*56
    int tid = threadIdx.x;
    int pb = blockIdx.x * 64;

    for (int t = tid; t < 192; t += 256) {
        int p = t / 3, a = t - p * 3;
        sX[p * 56 + a]      = pts[(pb + p) * 3 + a];
        sX[p * 56 + 3 + a]  = out[(size_t)NP * 5 + (pb + p) * 3 + a];   // gradients
        sX[p * 56 + 53 + a] = dirs[(pb + p) * 3 + a];
    }
    for (int t = tid; t < 2048; t += 256) { int p = t >> 5, c = t & 31; sX[p * 56 + 6 + c] = g_feats[pb * 32 + t]; }
    for (int t = tid; t < 960; t += 256) { int p = t / 15, j = t - p * 15; sX[p * 56 + 38 + j] = g_geo[pb * 15 + t]; }
    __syncthreads();

    gemm64x256(sX, 56, Wr0, 56, br0, sHr, sW, true, nullptr, nullptr);

    for (int t = tid; t < 768; t += 256) sW[t] = Wr1[t];
    __syncthreads();
    for (int o = tid; o < 192; o += 256) {
        int p = o / 3, c = o - p * 3;
        float a = br1[c];
        const float* hr = sHr + p * 256;
        for (int k = 0; k < 256; k++) a = fmaf(hr[k], sW[k * 3 + c], a);
        out[(size_t)(pb + p) * 3 + c] = 1.f / (1.f + expf(-a));
    }

    if (tid < 64) {
        int pt = pb + tid;
        float sdf = out[(size_t)NP * 4 + pt];
        float d   = deltas[pt];
        float gx = out[(size_t)NP * 5 + pt * 3],     gy = out[(size_t)NP * 5 + pt * 3 + 1],
              gz = out[(size_t)NP * 5 + pt * 3 + 2];
        float dx = dirs[pt * 3], dy = dirs[pt * 3 + 1], dz = dirs[pt * 3 + 2];
        float be = fabsf(beta[0]) + 1e-4f;
        float sg = (sdf > 0.f) ? 1.f : ((sdf < 0.f) ? -1.f : 0.f);
        float density = (0.5f + 0.5f * sg * expm1f(-fabsf(sdf) / be)) / be;
        float iv = expf(variance[0] * 10.f);
        iv = fminf(fmaxf(iv, 1e-6f), 1e6f);
        float tc = dx * gx + dy * gy + dz * gz;
        float ic = -fmaxf(-tc, 0.f);                 // COS_ANNEAL = 1
        float en = sdf + ic * d * 0.5f;
        float ep = sdf - ic * d * 0.5f;
        float pc = 1.f / (1.f + expf(-ep * iv));
        float nc = 1.f / (1.f + expf(-en * iv));
        float al = (pc - nc + 1e-5f) / (pc + 1e-5f);
        al = fminf(fmaxf(al, 0.f), 1.f);
        out[(size_t)NP * 3 + pt]  = density;
        out[(size_t)NP * 11 + pt] = al;
    }
}

// ---------------- launch ----------------
extern "C" void kernel_launch(void* const* d_in, const int* in_sizes, int n_in,
                              void* d_out, int out_size) {
    const float* points     = (const float*)d_in[0];
    const float* directions = (const float*)d_in[1];
    const float* deltas     = (const float*)d_in[2];
    const float* vol0       = (const float*)d_in[3];
    const float* vol1       = (const float*)d_in[4];
    const float* W0  = (const float*)d_in[5];
    const float* b0  = (const float*)d_in[6];
    const float* W1  = (const float*)d_in[7];
    const float* b1  = (const float*)d_in[8];
    const float* W2  = (const float*)d_in[9];
    const float* b2  = (const float*)d_in[10];
    const float* Wr0 = (const float*)d_in[11];
    const float* br0 = (const float*)d_in[12];
    const float* Wr1 = (const float*)d_in[13];
    const float* br1 = (const float*)d_in[14];
    const float* beta     = (const float*)d_in[15];
    const float* variance = (const float*)d_in[16];
    float* out = (float*)d_out;

    cudaFuncSetAttribute(k_forward,  cudaFuncAttributeMaxDynamicSharedMemorySize, 43264 * 4);
    cudaFuncSetAttribute(k_backward, cudaFuncAttributeMaxDynamicSharedMemorySize, 50368 * 4);
    cudaFuncSetAttribute(k_rgb,      cudaFuncAttributeMaxDynamicSharedMemorySize, 28160 * 4);

    k_transpose<<<128, 256>>>(W0, W1);
    k_sample<<<NP / 64, 64, 8320 * 4>>>(points, vol0, vol1);
    k_forward<<<NP / 64, 256, 43264 * 4>>>(points, W0, b0, W1, b1, W2, b2, out);
    k_backward<<<NP / 64, 256, 50368 * 4>>>(W2, out);
    k_rgb<<<NP / 64, 256, 28160 * 4>>>(points, directions, deltas,
                                       Wr0, br0, Wr1, br1, beta, variance, out);
}